// round 1
// baseline (speedup 1.0000x reference)
#include <cuda_runtime.h>
#include <cuda_bf16.h>

#define Bb   8
#define Nn   8192
#define Mm   64
#define KQ   3
#define KN   (KQ*Nn)        // 24576
#define PTOT (Bb*KN)        // 196608
#define SOMK 9
#define QTOT (Bb*Mm*SOMK)   // 4608
#define RTOT (Bb*Mm)        // 512
#define EPSF 1e-5f

// ---------------- scratch (device globals; no allocation) ----------------
__device__ float g_xaug[6*PTOT];
__device__ float g_h02[320*PTOT];     // rows 0..63 = h0, rows 64..319 = h2
__device__ float g_h1[128*PTOT];
__device__ int   g_seg[PTOT];         // b*M + node index per assignment column
__device__ float g_cnt[Bb*Mm];
__device__ float g_sum[Bb*3*Mm];
__device__ float g_cmean[Bb*3*Mm];
__device__ float g_center[Bb*3*Mm];
__device__ float g_nodeMax[RTOT*384]; // [(b*M+m)*384 + c]
__device__ float g_first0[Bb*384];
__device__ float g_aug[387*QTOT];
__device__ float g_g1[512*QTOT];
__device__ float g_g2[512*QTOT];
__device__ float g_finin[515*RTOT];
__device__ float g_f1[768*RTOT];
__device__ float g_f2[1024*RTOT];

// ---------------- zero kernels (stats must be cleared every call) --------
__global__ void k_zero_stats() {
    int i = blockIdx.x*blockDim.x + threadIdx.x;
    if (i < Bb*Mm)   g_cnt[i] = 0.f;
    if (i < Bb*3*Mm) g_sum[i] = 0.f;
}
__global__ void k_zero_nodemax() {
    int i = blockIdx.x*blockDim.x + threadIdx.x;
    if (i < RTOT*384) g_nodeMax[i] = 0.f;
}

// ---------------- step 1: per-point top-3 nearest SOM nodes + seg sums ---
__global__ void k_assign(const float* __restrict__ x, const float* __restrict__ node) {
    int b  = blockIdx.y;
    int n  = blockIdx.x*blockDim.x + threadIdx.x;
    int tid = threadIdx.x;
    __shared__ float snode[3][Mm];
    __shared__ float scnt[Mm];
    __shared__ float ssum[3][Mm];
    if (tid < 3*Mm) { int c = tid/Mm, m = tid%Mm; snode[c][m] = node[(b*3+c)*Mm+m]; }
    if (tid < Mm)   scnt[tid] = 0.f;
    if (tid < 3*Mm) ((float*)ssum)[tid] = 0.f;
    __syncthreads();

    float x0 = x[(b*3+0)*Nn+n], x1 = x[(b*3+1)*Nn+n], x2 = x[(b*3+2)*Nn+n];
    float d0 = 1e30f, d1 = 1e30f, d2 = 1e30f;
    int   i0 = 0, i1 = 0, i2 = 0;
    #pragma unroll 8
    for (int m = 0; m < Mm; m++) {
        float dx = x0 - snode[0][m], dy = x1 - snode[1][m], dz = x2 - snode[2][m];
        float d = dx*dx + dy*dy + dz*dz;
        if (d < d2) {
            if (d < d1) {
                if (d < d0) { d2=d1; i2=i1; d1=d0; i1=i0; d0=d; i0=m; }
                else        { d2=d1; i2=i1; d1=d;  i1=m; }
            } else          { d2=d;  i2=m; }
        }
    }
    g_seg[b*KN + 0*Nn + n] = b*Mm + i0;
    g_seg[b*KN + 1*Nn + n] = b*Mm + i1;
    g_seg[b*KN + 2*Nn + n] = b*Mm + i2;

    atomicAdd(&scnt[i0], 1.f); atomicAdd(&scnt[i1], 1.f); atomicAdd(&scnt[i2], 1.f);
    atomicAdd(&ssum[0][i0], x0); atomicAdd(&ssum[1][i0], x1); atomicAdd(&ssum[2][i0], x2);
    atomicAdd(&ssum[0][i1], x0); atomicAdd(&ssum[1][i1], x1); atomicAdd(&ssum[2][i1], x2);
    atomicAdd(&ssum[0][i2], x0); atomicAdd(&ssum[1][i2], x1); atomicAdd(&ssum[2][i2], x2);
    __syncthreads();
    if (tid < Mm)   atomicAdd(&g_cnt[b*Mm+tid], scnt[tid]);
    if (tid < 3*Mm) { int c = tid/Mm, m = tid%Mm; atomicAdd(&g_sum[(b*3+c)*Mm+m], ssum[c][m]); }
}

__global__ void k_mean() {
    int i = blockIdx.x*blockDim.x + threadIdx.x;   // B*3*M = 1536
    if (i >= Bb*3*Mm) return;
    int m = i % Mm; int b = (i/Mm)/3;
    g_cmean[i] = g_sum[i] / (g_cnt[b*Mm+m] + EPSF);
}

// ---------------- step 2: build decentered augmented input (6 x PTOT) ----
__global__ void k_xaug(const float* __restrict__ x, const float* __restrict__ sn) {
    int p = blockIdx.x*blockDim.x + threadIdx.x;
    if (p >= PTOT) return;
    int n = p % Nn;
    int b = p / KN;
    int nm = g_seg[p] % Mm;
    #pragma unroll
    for (int c = 0; c < 3; c++) {
        g_xaug[c*PTOT + p]     = x[(b*3+c)*Nn+n] - g_cmean[(b*3+c)*Mm+nm];
        g_xaug[(3+c)*PTOT + p] = sn[(b*3+c)*Nn+n];
    }
}

// ---------------- SGEMM: C = relu(A[MxK] * X[KxN] + bias) ----------------
#define BM 64
#define BN 64
#define BK 16
__global__ void k_gemm_relu(const float* __restrict__ A, const float* __restrict__ X,
                            const float* __restrict__ bias, float* __restrict__ C,
                            int Md, int Nd, int Kd) {
    __shared__ float As[BK][BM];
    __shared__ float Bs[BK][BN];
    int tid = threadIdx.y*16 + threadIdx.x;
    int rowBase = blockIdx.y*BM;
    int colBase = blockIdx.x*BN;
    float acc[4][4] = {};
    for (int k0 = 0; k0 < Kd; k0 += BK) {
        #pragma unroll
        for (int i = 0; i < 4; i++) {
            int e = tid + i*256; int m = e & 63, k = e >> 6;
            As[k][m] = (k0+k < Kd) ? A[(size_t)(rowBase+m)*Kd + k0+k] : 0.f;
        }
        #pragma unroll
        for (int i = 0; i < 4; i++) {
            int e = tid + i*256; int n = e & 63, k = e >> 6;
            Bs[k][n] = (k0+k < Kd) ? X[(size_t)(k0+k)*Nd + colBase+n] : 0.f;
        }
        __syncthreads();
        #pragma unroll
        for (int k = 0; k < BK; k++) {
            float4 a4 = *(const float4*)&As[k][threadIdx.y*4];
            float4 b4 = *(const float4*)&Bs[k][threadIdx.x*4];
            float a[4] = {a4.x,a4.y,a4.z,a4.w};
            float bb[4] = {b4.x,b4.y,b4.z,b4.w};
            #pragma unroll
            for (int i = 0; i < 4; i++)
                #pragma unroll
                for (int j = 0; j < 4; j++)
                    acc[i][j] += a[i]*bb[j];
        }
        __syncthreads();
    }
    #pragma unroll
    for (int i = 0; i < 4; i++) {
        int row = rowBase + threadIdx.y*4 + i;
        float bv = bias[row];
        #pragma unroll
        for (int j = 0; j < 4; j++) {
            int col = colBase + threadIdx.x*4 + j;
            float v = acc[i][j] + bv;
            v = v > 0.f ? v : 0.f;
            C[(size_t)row*Nd + col] = v;
        }
    }
}

// GEMM with fused segment-max epilogue (post-ReLU values >= 0 -> int atomicMax OK)
__global__ void k_gemm_relu_segmax(const float* __restrict__ A,
                                   const float* __restrict__ X,
                                   const float* __restrict__ bias,
                                   int Md, int Nd, int Kd) {
    __shared__ float As[BK][BM];
    __shared__ float Bs[BK][BN];
    int tid = threadIdx.y*16 + threadIdx.x;
    int rowBase = blockIdx.y*BM;
    int colBase = blockIdx.x*BN;
    float acc[4][4] = {};
    for (int k0 = 0; k0 < Kd; k0 += BK) {
        #pragma unroll
        for (int i = 0; i < 4; i++) {
            int e = tid + i*256; int m = e & 63, k = e >> 6;
            As[k][m] = (k0+k < Kd) ? A[(size_t)(rowBase+m)*Kd + k0+k] : 0.f;
        }
        #pragma unroll
        for (int i = 0; i < 4; i++) {
            int e = tid + i*256; int n = e & 63, k = e >> 6;
            Bs[k][n] = (k0+k < Kd) ? X[(size_t)(k0+k)*Nd + colBase+n] : 0.f;
        }
        __syncthreads();
        #pragma unroll
        for (int k = 0; k < BK; k++) {
            float4 a4 = *(const float4*)&As[k][threadIdx.y*4];
            float4 b4 = *(const float4*)&Bs[k][threadIdx.x*4];
            float a[4] = {a4.x,a4.y,a4.z,a4.w};
            float bb[4] = {b4.x,b4.y,b4.z,b4.w};
            #pragma unroll
            for (int i = 0; i < 4; i++)
                #pragma unroll
                for (int j = 0; j < 4; j++)
                    acc[i][j] += a[i]*bb[j];
        }
        __syncthreads();
    }
    #pragma unroll
    for (int j = 0; j < 4; j++) {
        int col = colBase + threadIdx.x*4 + j;
        int s = g_seg[col];
        #pragma unroll
        for (int i = 0; i < 4; i++) {
            int row = rowBase + threadIdx.y*4 + i;
            float v = acc[i][j] + bias[row];
            v = v > 0.f ? v : 0.f;
            atomicMax((int*)&g_nodeMax[(size_t)s*384 + row], __float_as_int(v));
            if ((col % KN) == 0) g_first0[(col/KN)*384 + row] = v;
        }
    }
}

// ---------------- KNN module prep -----------------------------------------
__global__ void k_center(const int* __restrict__ I) {
    int i = blockIdx.x*blockDim.x + threadIdx.x;   // B*3*M
    if (i >= Bb*3*Mm) return;
    int m = i % Mm; int bc = i / Mm; int b = bc/3; int c = bc%3;
    float s = 0.f;
    #pragma unroll
    for (int kk = 0; kk < SOMK; kk++) {
        int im = I[(b*Mm+m)*SOMK + kk];
        s += g_cmean[(b*3+c)*Mm + im];
    }
    g_center[i] = s * (1.0f/SOMK);
}

__global__ void k_aug(const int* __restrict__ I) {
    int t = blockIdx.x*blockDim.x + threadIdx.x;   // 387*QTOT
    if (t >= 387*QTOT) return;
    int q = t % QTOT, c = t / QTOT;
    int kk = q % SOMK; int bm = q / SOMK; int b = bm / Mm; int m = bm % Mm;
    int im = I[bm*SOMK + kk];
    float v;
    if (c < 3)
        v = g_cmean[(b*3+c)*Mm + im] - g_center[(b*3+c)*Mm + m];
    else
        v = (g_cnt[b*Mm+im] > 0.f) ? g_nodeMax[(size_t)(b*Mm+im)*384 + (c-3)]
                                   : g_first0[b*384 + (c-3)];
    g_aug[(size_t)c*QTOT + q] = v;
}

// max over som_k neighbors + assemble final PointNet input (515 x RTOT)
__global__ void k_finin() {
    int t = blockIdx.x*blockDim.x + threadIdx.x;   // 515*RTOT
    if (t >= 515*RTOT) return;
    int r = t % RTOT, c = t / RTOT;
    float v;
    if (c < 3) {
        int b = r / Mm, m = r % Mm;
        v = g_center[(b*3+c)*Mm + m];
    } else {
        float mx = -1e30f;
        size_t base = (size_t)(c-3)*QTOT + (size_t)r*SOMK;
        #pragma unroll
        for (int kk = 0; kk < SOMK; kk++) mx = fmaxf(mx, g_g2[base+kk]);
        v = mx;
    }
    g_finin[(size_t)c*RTOT + r] = v;
}

// global max pool over M nodes -> output (B,1024)
__global__ void k_out(float* __restrict__ out) {
    int t = blockIdx.x*blockDim.x + threadIdx.x;   // B*1024
    if (t >= Bb*1024) return;
    int c = t % 1024, b = t / 1024;
    float mx = -1e30f;
    #pragma unroll 8
    for (int m = 0; m < Mm; m++) mx = fmaxf(mx, g_f2[(size_t)c*RTOT + b*Mm + m]);
    out[t] = mx;
}

// ---------------- launch ---------------------------------------------------
extern "C" void kernel_launch(void* const* d_in, const int* in_sizes, int n_in,
                              void* d_out, int out_size) {
    const float* x       = (const float*)d_in[0];
    const float* sn      = (const float*)d_in[1];
    const float* node    = (const float*)d_in[2];
    const int*   knnI    = (const int*)  d_in[3];
    const float* pr_w0   = (const float*)d_in[4];
    const float* pr_b0   = (const float*)d_in[5];
    const float* pr_w1   = (const float*)d_in[6];
    const float* pr_b1   = (const float*)d_in[7];
    const float* pr_w2   = (const float*)d_in[8];
    const float* pr_b2   = (const float*)d_in[9];
    const float* pr_w3   = (const float*)d_in[10];
    const float* pr_b3   = (const float*)d_in[11];
    const float* knn_w0  = (const float*)d_in[12];
    const float* knn_b0  = (const float*)d_in[13];
    const float* knn_w1  = (const float*)d_in[14];
    const float* knn_b1  = (const float*)d_in[15];
    const float* fin_w0  = (const float*)d_in[16];
    const float* fin_b0  = (const float*)d_in[17];
    const float* fin_w1  = (const float*)d_in[18];
    const float* fin_b1  = (const float*)d_in[19];
    float* out = (float*)d_out;

    // scratch pointers (symbol lookup each call; capture-safe, no allocation)
    float *p_xaug, *p_h02, *p_h1, *p_aug, *p_g1, *p_g2, *p_finin, *p_f1, *p_f2;
    cudaGetSymbolAddress((void**)&p_xaug,  g_xaug);
    cudaGetSymbolAddress((void**)&p_h02,   g_h02);
    cudaGetSymbolAddress((void**)&p_h1,    g_h1);
    cudaGetSymbolAddress((void**)&p_aug,   g_aug);
    cudaGetSymbolAddress((void**)&p_g1,    g_g1);
    cudaGetSymbolAddress((void**)&p_g2,    g_g2);
    cudaGetSymbolAddress((void**)&p_finin, g_finin);
    cudaGetSymbolAddress((void**)&p_f1,    g_f1);
    cudaGetSymbolAddress((void**)&p_f2,    g_f2);

    dim3 tpb(16,16);

    k_zero_stats  <<<(Bb*3*Mm + 255)/256, 256>>>();
    k_zero_nodemax<<<(RTOT*384 + 255)/256, 256>>>();

    k_assign<<<dim3(Nn/256, Bb), 256>>>(x, node);
    k_mean  <<<(Bb*3*Mm + 255)/256, 256>>>();
    k_xaug  <<<(PTOT + 255)/256, 256>>>(x, sn);

    // PointResNet
    k_gemm_relu<<<dim3(PTOT/BN, 64/BM),  tpb>>>(pr_w0, p_xaug, pr_b0, p_h02,               64,  PTOT, 6);
    k_gemm_relu<<<dim3(PTOT/BN, 128/BM), tpb>>>(pr_w1, p_h02,  pr_b1, p_h1,                128, PTOT, 64);
    k_gemm_relu<<<dim3(PTOT/BN, 256/BM), tpb>>>(pr_w2, p_h1,   pr_b2, p_h02 + (size_t)64*PTOT, 256, PTOT, 128);
    k_gemm_relu_segmax<<<dim3(PTOT/BN, 384/BM), tpb>>>(pr_w3, p_h02, pr_b3, 384, PTOT, 320);

    // KNN module over SOM nodes
    k_center<<<(Bb*3*Mm + 255)/256, 256>>>(knnI);
    k_aug   <<<(387*QTOT + 255)/256, 256>>>(knnI);
    k_gemm_relu<<<dim3(QTOT/BN, 512/BM), tpb>>>(knn_w0, p_aug, knn_b0, p_g1, 512, QTOT, 387);
    k_gemm_relu<<<dim3(QTOT/BN, 512/BM), tpb>>>(knn_w1, p_g1,  knn_b1, p_g2, 512, QTOT, 512);

    // final PointNet + global max
    k_finin<<<(515*RTOT + 255)/256, 256>>>();
    k_gemm_relu<<<dim3(RTOT/BN, 768/BM),  tpb>>>(fin_w0, p_finin, fin_b0, p_f1, 768,  RTOT, 515);
    k_gemm_relu<<<dim3(RTOT/BN, 1024/BM), tpb>>>(fin_w1, p_f1,    fin_b1, p_f2, 1024, RTOT, 768);
    k_out<<<(Bb*1024 + 255)/256, 256>>>(out);
}

// round 2
// speedup vs baseline: 4.2966x; 4.2966x over previous
#include <cuda_runtime.h>
#include <cuda_bf16.h>
#include <cstdint>

#define Bb   8
#define Nn   8192
#define Mm   64
#define KQ   3
#define KN   (KQ*Nn)        // 24576
#define PTOT (Bb*KN)        // 196608
#define SOMK 9
#define QTOT (Bb*Mm*SOMK)   // 4608
#define RTOT (Bb*Mm)        // 512
#define EPSF 1e-5f

// ---------------- scratch (device globals; no allocation) ----------------
__device__ float g_xaug[6*PTOT];
__device__ float g_h02[320*PTOT];     // rows 0..63 = h0, rows 64..319 = h2
__device__ float g_h1[128*PTOT];
__device__ int   g_seg[PTOT];         // b*M + node index per assignment column
__device__ float g_cnt[Bb*Mm];
__device__ float g_sum[Bb*3*Mm];
__device__ float g_cmean[Bb*3*Mm];
__device__ float g_center[Bb*3*Mm];
__device__ float g_nodeMax[RTOT*384]; // [(b*M+m)*384 + c]
__device__ float g_first0[Bb*384];
__device__ float g_aug[387*QTOT];
__device__ float g_g1[512*QTOT];
__device__ float g_g2[512*QTOT];
__device__ float g_finin[515*RTOT];
__device__ float g_f1[768*RTOT];
__device__ float g_f2[1024*RTOT];

// ---------------- zero kernels -------------------------------------------
__global__ void k_zero_stats() {
    int i = blockIdx.x*blockDim.x + threadIdx.x;
    if (i < Bb*Mm)   g_cnt[i] = 0.f;
    if (i < Bb*3*Mm) g_sum[i] = 0.f;
}
__global__ void k_zero_nodemax() {
    int i = blockIdx.x*blockDim.x + threadIdx.x;
    if (i < RTOT*384) g_nodeMax[i] = 0.f;
}

// ---------------- step 1: per-point top-3 nearest SOM nodes + seg sums ---
__global__ void k_assign(const float* __restrict__ x, const float* __restrict__ node) {
    int b  = blockIdx.y;
    int n  = blockIdx.x*blockDim.x + threadIdx.x;
    int tid = threadIdx.x;
    __shared__ float snode[3][Mm];
    __shared__ float scnt[Mm];
    __shared__ float ssum[3][Mm];
    if (tid < 3*Mm) { int c = tid/Mm, m = tid%Mm; snode[c][m] = node[(b*3+c)*Mm+m]; }
    if (tid < Mm)   scnt[tid] = 0.f;
    if (tid < 3*Mm) ((float*)ssum)[tid] = 0.f;
    __syncthreads();

    float x0 = x[(b*3+0)*Nn+n], x1 = x[(b*3+1)*Nn+n], x2 = x[(b*3+2)*Nn+n];
    float d0 = 1e30f, d1 = 1e30f, d2 = 1e30f;
    int   i0 = 0, i1 = 0, i2 = 0;
    #pragma unroll 8
    for (int m = 0; m < Mm; m++) {
        float dx = x0 - snode[0][m], dy = x1 - snode[1][m], dz = x2 - snode[2][m];
        float d = dx*dx + dy*dy + dz*dz;
        if (d < d2) {
            if (d < d1) {
                if (d < d0) { d2=d1; i2=i1; d1=d0; i1=i0; d0=d; i0=m; }
                else        { d2=d1; i2=i1; d1=d;  i1=m; }
            } else          { d2=d;  i2=m; }
        }
    }
    g_seg[b*KN + 0*Nn + n] = b*Mm + i0;
    g_seg[b*KN + 1*Nn + n] = b*Mm + i1;
    g_seg[b*KN + 2*Nn + n] = b*Mm + i2;

    atomicAdd(&scnt[i0], 1.f); atomicAdd(&scnt[i1], 1.f); atomicAdd(&scnt[i2], 1.f);
    atomicAdd(&ssum[0][i0], x0); atomicAdd(&ssum[1][i0], x1); atomicAdd(&ssum[2][i0], x2);
    atomicAdd(&ssum[0][i1], x0); atomicAdd(&ssum[1][i1], x1); atomicAdd(&ssum[2][i1], x2);
    atomicAdd(&ssum[0][i2], x0); atomicAdd(&ssum[1][i2], x1); atomicAdd(&ssum[2][i2], x2);
    __syncthreads();
    if (tid < Mm)   atomicAdd(&g_cnt[b*Mm+tid], scnt[tid]);
    if (tid < 3*Mm) { int c = tid/Mm, m = tid%Mm; atomicAdd(&g_sum[(b*3+c)*Mm+m], ssum[c][m]); }
}

__global__ void k_mean() {
    int i = blockIdx.x*blockDim.x + threadIdx.x;   // B*3*M = 1536
    if (i >= Bb*3*Mm) return;
    int m = i % Mm; int b = (i/Mm)/3;
    g_cmean[i] = g_sum[i] / (g_cnt[b*Mm+m] + EPSF);
}

// ---------------- step 2: build decentered augmented input (6 x PTOT) ----
__global__ void k_xaug(const float* __restrict__ x, const float* __restrict__ sn) {
    int p = blockIdx.x*blockDim.x + threadIdx.x;
    if (p >= PTOT) return;
    int n = p % Nn;
    int b = p / KN;
    int nm = g_seg[p] % Mm;
    #pragma unroll
    for (int c = 0; c < 3; c++) {
        g_xaug[c*PTOT + p]     = x[(b*3+c)*Nn+n] - g_cmean[(b*3+c)*Mm+nm];
        g_xaug[(3+c)*PTOT + p] = sn[(b*3+c)*Nn+n];
    }
}

// ---------------- FFMA SGEMM (kept only for gemm1, K=6, memory-bound) ----
#define BM 64
#define BN 64
#define BK 16
__global__ void k_gemm_relu(const float* __restrict__ A, const float* __restrict__ X,
                            const float* __restrict__ bias, float* __restrict__ C,
                            int Md, int Nd, int Kd) {
    __shared__ float As[BK][BM];
    __shared__ float Bs[BK][BN];
    int tid = threadIdx.y*16 + threadIdx.x;
    int rowBase = blockIdx.y*BM;
    int colBase = blockIdx.x*BN;
    float acc[4][4] = {};
    for (int k0 = 0; k0 < Kd; k0 += BK) {
        #pragma unroll
        for (int i = 0; i < 4; i++) {
            int e = tid + i*256; int m = e & 63, k = e >> 6;
            As[k][m] = (k0+k < Kd) ? A[(size_t)(rowBase+m)*Kd + k0+k] : 0.f;
        }
        #pragma unroll
        for (int i = 0; i < 4; i++) {
            int e = tid + i*256; int n = e & 63, k = e >> 6;
            Bs[k][n] = (k0+k < Kd) ? X[(size_t)(k0+k)*Nd + colBase+n] : 0.f;
        }
        __syncthreads();
        #pragma unroll
        for (int k = 0; k < BK; k++) {
            float4 a4 = *(const float4*)&As[k][threadIdx.y*4];
            float4 b4 = *(const float4*)&Bs[k][threadIdx.x*4];
            float a[4] = {a4.x,a4.y,a4.z,a4.w};
            float bb[4] = {b4.x,b4.y,b4.z,b4.w};
            #pragma unroll
            for (int i = 0; i < 4; i++)
                #pragma unroll
                for (int j = 0; j < 4; j++)
                    acc[i][j] += a[i]*bb[j];
        }
        __syncthreads();
    }
    #pragma unroll
    for (int i = 0; i < 4; i++) {
        int row = rowBase + threadIdx.y*4 + i;
        float bv = bias[row];
        #pragma unroll
        for (int j = 0; j < 4; j++) {
            int col = colBase + threadIdx.x*4 + j;
            float v = acc[i][j] + bv;
            v = v > 0.f ? v : 0.f;
            C[(size_t)row*Nd + col] = v;
        }
    }
}

// ---------------- TF32 tensor-core GEMM ----------------------------------
// C[Md x Nd] = relu(A[Md x Kd] * X[Kd x Nd] + bias), Md%128==0, Nd%128==0.
// Block tile 128x128xBK16, 8 warps (4x2), warp tile 32x64, mma.m16n8k8.tf32.
#define BMT 128
#define BNT 128
#define BKT 16
#define LDT (128+4)   // smem row pitch (floats), +4 kills frag-read conflicts

__device__ __forceinline__ uint32_t f2tf(float f) {
    uint32_t u; asm("cvt.rna.tf32.f32 %0, %1;" : "=r"(u) : "f"(f)); return u;
}
__device__ __forceinline__ void mma_tf32(float c[4],
        uint32_t a0, uint32_t a1, uint32_t a2, uint32_t a3,
        uint32_t b0, uint32_t b1) {
    asm volatile(
        "mma.sync.aligned.m16n8k8.row.col.f32.tf32.tf32.f32 "
        "{%0,%1,%2,%3}, {%4,%5,%6,%7}, {%8,%9}, {%0,%1,%2,%3};"
        : "+f"(c[0]), "+f"(c[1]), "+f"(c[2]), "+f"(c[3])
        : "r"(a0), "r"(a1), "r"(a2), "r"(a3), "r"(b0), "r"(b1));
}

template<int SEGMAX>
__global__ __launch_bounds__(256)
void k_mma_gemm(const float* __restrict__ A, const float* __restrict__ X,
                const float* __restrict__ bias, float* __restrict__ C,
                int Nd, int Kd) {
    __shared__ uint32_t As[2][BKT][LDT];   // [k][m], tf32 bits
    __shared__ uint32_t Bs[2][BKT][LDT];   // [k][n], tf32 bits
    const int tid  = threadIdx.x;
    const int lane = tid & 31, warp = tid >> 5;
    const int wm = warp & 3, wn = warp >> 2;           // 4 (M) x 2 (N)
    const int g  = lane >> 2, t4 = lane & 3;
    const int rowBase = blockIdx.y * BMT;
    const int colBase = blockIdx.x * BNT;
    const int mW = wm * 32, nW = wn * 64;

    float acc[2][8][4];
    #pragma unroll
    for (int i = 0; i < 2; i++)
        #pragma unroll
        for (int j = 0; j < 8; j++)
            #pragma unroll
            for (int l = 0; l < 4; l++) acc[i][j][l] = 0.f;

    const int nT = (Kd + BKT - 1) / BKT;
    float  aSt[8];
    float4 xSt[2];

    auto loadG = [&](int t) {
        int k0 = t * BKT;
        #pragma unroll
        for (int i = 0; i < 8; i++) {
            int e = tid + i*256; int k = e & 15, m = e >> 4;
            aSt[i] = (k0 + k < Kd) ? A[(size_t)(rowBase + m)*Kd + k0 + k] : 0.f;
        }
        #pragma unroll
        for (int i = 0; i < 2; i++) {
            int e = tid + i*256; int n4 = e & 31, k = e >> 5;
            if (k0 + k < Kd) xSt[i] = *(const float4*)&X[(size_t)(k0 + k)*Nd + colBase + n4*4];
            else             xSt[i] = make_float4(0.f, 0.f, 0.f, 0.f);
        }
    };
    auto stS = [&](int buf) {
        #pragma unroll
        for (int i = 0; i < 8; i++) {
            int e = tid + i*256; int k = e & 15, m = e >> 4;
            As[buf][k][m] = f2tf(aSt[i]);
        }
        #pragma unroll
        for (int i = 0; i < 2; i++) {
            int e = tid + i*256; int n4 = e & 31, k = e >> 5;
            Bs[buf][k][n4*4+0] = f2tf(xSt[i].x);
            Bs[buf][k][n4*4+1] = f2tf(xSt[i].y);
            Bs[buf][k][n4*4+2] = f2tf(xSt[i].z);
            Bs[buf][k][n4*4+3] = f2tf(xSt[i].w);
        }
    };

    loadG(0); stS(0); __syncthreads();
    int buf = 0;
    for (int t = 0; t < nT; t++) {
        if (t + 1 < nT) loadG(t + 1);
        #pragma unroll
        for (int ks = 0; ks < BKT; ks += 8) {
            uint32_t af[2][4];
            #pragma unroll
            for (int mt = 0; mt < 2; mt++) {
                int m0 = mW + mt*16 + g;
                af[mt][0] = As[buf][ks + t4    ][m0];
                af[mt][1] = As[buf][ks + t4    ][m0 + 8];
                af[mt][2] = As[buf][ks + t4 + 4][m0];
                af[mt][3] = As[buf][ks + t4 + 4][m0 + 8];
            }
            #pragma unroll
            for (int nt = 0; nt < 8; nt++) {
                int n0 = nW + nt*8 + g;
                uint32_t b0 = Bs[buf][ks + t4    ][n0];
                uint32_t b1 = Bs[buf][ks + t4 + 4][n0];
                #pragma unroll
                for (int mt = 0; mt < 2; mt++)
                    mma_tf32(acc[mt][nt], af[mt][0], af[mt][1], af[mt][2], af[mt][3], b0, b1);
            }
        }
        if (t + 1 < nT) { stS(buf ^ 1); __syncthreads(); buf ^= 1; }
    }

    // epilogue
    #pragma unroll
    for (int mt = 0; mt < 2; mt++) {
        int r0 = rowBase + mW + mt*16 + g;
        float bv0 = bias[r0], bv1 = bias[r0 + 8];
        #pragma unroll
        for (int nt = 0; nt < 8; nt++) {
            int col = colBase + nW + nt*8 + t4*2;
            float v00 = fmaxf(acc[mt][nt][0] + bv0, 0.f);
            float v01 = fmaxf(acc[mt][nt][1] + bv0, 0.f);
            float v10 = fmaxf(acc[mt][nt][2] + bv1, 0.f);
            float v11 = fmaxf(acc[mt][nt][3] + bv1, 0.f);
            if (SEGMAX == 0) {
                *(float2*)&C[(size_t)r0*Nd + col]       = make_float2(v00, v01);
                *(float2*)&C[(size_t)(r0 + 8)*Nd + col] = make_float2(v10, v11);
            } else {
                int s0 = g_seg[col], s1 = g_seg[col + 1];
                atomicMax((int*)&g_nodeMax[(size_t)s0*384 + r0],     __float_as_int(v00));
                atomicMax((int*)&g_nodeMax[(size_t)s1*384 + r0],     __float_as_int(v01));
                atomicMax((int*)&g_nodeMax[(size_t)s0*384 + r0 + 8], __float_as_int(v10));
                atomicMax((int*)&g_nodeMax[(size_t)s1*384 + r0 + 8], __float_as_int(v11));
                if ((col % KN) == 0) {   // col is even; KN even => only col can hit
                    g_first0[(col/KN)*384 + r0]     = v00;
                    g_first0[(col/KN)*384 + r0 + 8] = v10;
                }
            }
        }
    }
}

// ---------------- KNN module prep -----------------------------------------
__global__ void k_center(const int* __restrict__ I) {
    int i = blockIdx.x*blockDim.x + threadIdx.x;   // B*3*M
    if (i >= Bb*3*Mm) return;
    int m = i % Mm; int bc = i / Mm; int b = bc/3; int c = bc%3;
    float s = 0.f;
    #pragma unroll
    for (int kk = 0; kk < SOMK; kk++) {
        int im = I[(b*Mm+m)*SOMK + kk];
        s += g_cmean[(b*3+c)*Mm + im];
    }
    g_center[i] = s * (1.0f/SOMK);
}

__global__ void k_aug(const int* __restrict__ I) {
    int t = blockIdx.x*blockDim.x + threadIdx.x;   // 387*QTOT
    if (t >= 387*QTOT) return;
    int q = t % QTOT, c = t / QTOT;
    int kk = q % SOMK; int bm = q / SOMK; int b = bm / Mm; int m = bm % Mm;
    int im = I[bm*SOMK + kk];
    float v;
    if (c < 3)
        v = g_cmean[(b*3+c)*Mm + im] - g_center[(b*3+c)*Mm + m];
    else
        v = (g_cnt[b*Mm+im] > 0.f) ? g_nodeMax[(size_t)(b*Mm+im)*384 + (c-3)]
                                   : g_first0[b*384 + (c-3)];
    g_aug[(size_t)c*QTOT + q] = v;
}

// max over som_k neighbors + assemble final PointNet input (515 x RTOT)
__global__ void k_finin() {
    int t = blockIdx.x*blockDim.x + threadIdx.x;   // 515*RTOT
    if (t >= 515*RTOT) return;
    int r = t % RTOT, c = t / RTOT;
    float v;
    if (c < 3) {
        int b = r / Mm, m = r % Mm;
        v = g_center[(b*3+c)*Mm + m];
    } else {
        float mx = -1e30f;
        size_t base = (size_t)(c-3)*QTOT + (size_t)r*SOMK;
        #pragma unroll
        for (int kk = 0; kk < SOMK; kk++) mx = fmaxf(mx, g_g2[base+kk]);
        v = mx;
    }
    g_finin[(size_t)c*RTOT + r] = v;
}

// global max pool over M nodes -> output (B,1024)
__global__ void k_out(float* __restrict__ out) {
    int t = blockIdx.x*blockDim.x + threadIdx.x;   // B*1024
    if (t >= Bb*1024) return;
    int c = t % 1024, b = t / 1024;
    float mx = -1e30f;
    #pragma unroll 8
    for (int m = 0; m < Mm; m++) mx = fmaxf(mx, g_f2[(size_t)c*RTOT + b*Mm + m]);
    out[t] = mx;
}

// ---------------- launch ---------------------------------------------------
extern "C" void kernel_launch(void* const* d_in, const int* in_sizes, int n_in,
                              void* d_out, int out_size) {
    const float* x       = (const float*)d_in[0];
    const float* sn      = (const float*)d_in[1];
    const float* node    = (const float*)d_in[2];
    const int*   knnI    = (const int*)  d_in[3];
    const float* pr_w0   = (const float*)d_in[4];
    const float* pr_b0   = (const float*)d_in[5];
    const float* pr_w1   = (const float*)d_in[6];
    const float* pr_b1   = (const float*)d_in[7];
    const float* pr_w2   = (const float*)d_in[8];
    const float* pr_b2   = (const float*)d_in[9];
    const float* pr_w3   = (const float*)d_in[10];
    const float* pr_b3   = (const float*)d_in[11];
    const float* knn_w0  = (const float*)d_in[12];
    const float* knn_b0  = (const float*)d_in[13];
    const float* knn_w1  = (const float*)d_in[14];
    const float* knn_b1  = (const float*)d_in[15];
    const float* fin_w0  = (const float*)d_in[16];
    const float* fin_b0  = (const float*)d_in[17];
    const float* fin_w1  = (const float*)d_in[18];
    const float* fin_b1  = (const float*)d_in[19];
    float* out = (float*)d_out;

    float *p_xaug, *p_h02, *p_h1, *p_aug, *p_g1, *p_g2, *p_finin, *p_f1, *p_f2;
    cudaGetSymbolAddress((void**)&p_xaug,  g_xaug);
    cudaGetSymbolAddress((void**)&p_h02,   g_h02);
    cudaGetSymbolAddress((void**)&p_h1,    g_h1);
    cudaGetSymbolAddress((void**)&p_aug,   g_aug);
    cudaGetSymbolAddress((void**)&p_g1,    g_g1);
    cudaGetSymbolAddress((void**)&p_g2,    g_g2);
    cudaGetSymbolAddress((void**)&p_finin, g_finin);
    cudaGetSymbolAddress((void**)&p_f1,    g_f1);
    cudaGetSymbolAddress((void**)&p_f2,    g_f2);

    dim3 tpb(16,16);

    k_zero_stats  <<<(Bb*3*Mm + 255)/256, 256>>>();
    k_zero_nodemax<<<(RTOT*384 + 255)/256, 256>>>();

    k_assign<<<dim3(Nn/256, Bb), 256>>>(x, node);
    k_mean  <<<(Bb*3*Mm + 255)/256, 256>>>();
    k_xaug  <<<(PTOT + 255)/256, 256>>>(x, sn);

    // PointResNet: gemm1 stays FFMA (K=6, memory-bound); rest on tensor pipe
    k_gemm_relu<<<dim3(PTOT/BN, 64/BM), tpb>>>(pr_w0, p_xaug, pr_b0, p_h02, 64, PTOT, 6);
    k_mma_gemm<0><<<dim3(PTOT/BNT, 128/BMT), 256>>>(pr_w1, p_h02, pr_b1, p_h1, PTOT, 64);
    k_mma_gemm<0><<<dim3(PTOT/BNT, 256/BMT), 256>>>(pr_w2, p_h1,  pr_b2, p_h02 + (size_t)64*PTOT, PTOT, 128);
    k_mma_gemm<1><<<dim3(PTOT/BNT, 384/BMT), 256>>>(pr_w3, p_h02, pr_b3, nullptr, PTOT, 320);

    // KNN module over SOM nodes
    k_center<<<(Bb*3*Mm + 255)/256, 256>>>(knnI);
    k_aug   <<<(387*QTOT + 255)/256, 256>>>(knnI);
    k_mma_gemm<0><<<dim3(QTOT/BNT, 512/BMT), 256>>>(knn_w0, p_aug, knn_b0, p_g1, QTOT, 387);
    k_mma_gemm<0><<<dim3(QTOT/BNT, 512/BMT), 256>>>(knn_w1, p_g1,  knn_b1, p_g2, QTOT, 512);

    // final PointNet + global max
    k_finin<<<(515*RTOT + 255)/256, 256>>>();
    k_mma_gemm<0><<<dim3(RTOT/BNT, 768/BMT),  256>>>(fin_w0, p_finin, fin_b0, p_f1, RTOT, 515);
    k_mma_gemm<0><<<dim3(RTOT/BNT, 1024/BMT), 256>>>(fin_w1, p_f1,    fin_b1, p_f2, RTOT, 768);
    k_out<<<(Bb*1024 + 255)/256, 256>>>(out);
}

// round 5
// speedup vs baseline: 8.9261x; 2.0775x over previous
#include <cuda_runtime.h>
#include <cuda_fp16.h>
#include <cstdint>

// ---------------- problem dims --------------------------------------------
#define Bb   8
#define Nn   8192
#define Mm   64
#define KQ   3
#define KN   (KQ*Nn)        // 24576
#define PTOT (Bb*KN)        // 196608
#define SOMK 9
#define QTOT (Bb*Mm*SOMK)   // 4608
#define RTOT (Bb*Mm)        // 512
#define EPSF 1e-5f
#define K_AUG 416           // 387 padded to mult of 32
#define K_FIN 544           // 515 padded to mult of 32

// ---------------- scratch (device globals; no allocation) -----------------
// activations CHANNEL-MAJOR fp16: row = channel, col = point
__device__ __half g_h02[(size_t)320*PTOT];   // rows 0..63 = h0, 64..319 = h2
__device__ __half g_h1[(size_t)128*PTOT];
__device__ int    g_seg[PTOT];
__device__ float  g_cnt[Bb*Mm];
__device__ float  g_sum[Bb*3*Mm];
__device__ float  g_cmean[Bb*3*Mm];
__device__ float  g_center[Bb*3*Mm];
__device__ float  g_nodeMax[RTOT*384];
__device__ float  g_first0[Bb*384];
__device__ __half g_aug[(size_t)K_AUG*QTOT];
__device__ __half g_g1[(size_t)512*QTOT];
__device__ __half g_g2[(size_t)512*QTOT];
__device__ __half g_finin[(size_t)K_FIN*RTOT];
__device__ __half g_f1[(size_t)768*RTOT];
__device__ float  g_f2[(size_t)1024*RTOT];   // final layer kept fp32
// fp16 weight copies [o][k], K zero-padded where needed
__device__ __half g_w1[128*64];
__device__ __half g_w2[256*128];
__device__ __half g_w3[384*320];
__device__ __half g_kw0[512*K_AUG];
__device__ __half g_kw1[512*512];
__device__ __half g_fw0[768*K_FIN];
__device__ __half g_fw1[1024*768];

// ---------------- PTX helpers ---------------------------------------------
__device__ __forceinline__ uint32_t smem_u32(const void* p) {
    uint32_t a;
    asm("{ .reg .u64 t; cvta.to.shared.u64 t, %1; cvt.u32.u64 %0, t; }" : "=r"(a) : "l"(p));
    return a;
}
#define CPA16(dst, src) \
    asm volatile("cp.async.cg.shared.global [%0], [%1], 16;" :: "r"(dst), "l"(src))
#define CPA_COMMIT() asm volatile("cp.async.commit_group;" ::: "memory")
#define CPA_WAIT(n)  asm volatile("cp.async.wait_group %0;" :: "n"(n) : "memory")

#define LDSM4(r0,r1,r2,r3,addr) \
    asm volatile("ldmatrix.sync.aligned.m8n8.x4.shared.b16 {%0,%1,%2,%3}, [%4];" \
        : "=r"(r0), "=r"(r1), "=r"(r2), "=r"(r3) : "r"(addr))
#define LDSM4T(r0,r1,r2,r3,addr) \
    asm volatile("ldmatrix.sync.aligned.m8n8.x4.trans.shared.b16 {%0,%1,%2,%3}, [%4];" \
        : "=r"(r0), "=r"(r1), "=r"(r2), "=r"(r3) : "r"(addr))

__device__ __forceinline__ void mma16816(float c[4], uint32_t a0, uint32_t a1,
                                         uint32_t a2, uint32_t a3,
                                         uint32_t b0, uint32_t b1) {
    asm volatile(
        "mma.sync.aligned.m16n8k16.row.col.f32.f16.f16.f32 "
        "{%0,%1,%2,%3}, {%4,%5,%6,%7}, {%8,%9}, {%0,%1,%2,%3};"
        : "+f"(c[0]), "+f"(c[1]), "+f"(c[2]), "+f"(c[3])
        : "r"(a0), "r"(a1), "r"(a2), "r"(a3), "r"(b0), "r"(b1));
}

// ---------------- zero kernels --------------------------------------------
__global__ void k_zero_stats() {
    int i = blockIdx.x*blockDim.x + threadIdx.x;
    if (i < Bb*Mm)   g_cnt[i] = 0.f;
    if (i < Bb*3*Mm) g_sum[i] = 0.f;
}
__global__ void k_zero_nodemax() {
    int i = blockIdx.x*blockDim.x + threadIdx.x;
    if (i < RTOT*384) g_nodeMax[i] = 0.f;
}

// ---------------- weight prep: fp16 round + zero-pad K ---------------------
__global__ void k_wprep(const float* __restrict__ w1, const float* __restrict__ w2,
                        const float* __restrict__ w3, const float* __restrict__ kw0,
                        const float* __restrict__ kw1, const float* __restrict__ fw0,
                        const float* __restrict__ fw1) {
    int i = blockIdx.x*blockDim.x + threadIdx.x;
    if (i < 128*64)  { g_w1[i] = __float2half_rn(w1[i]); return; }  i -= 128*64;
    if (i < 256*128) { g_w2[i] = __float2half_rn(w2[i]); return; }  i -= 256*128;
    if (i < 384*320) { g_w3[i] = __float2half_rn(w3[i]); return; }  i -= 384*320;
    if (i < 512*K_AUG) { int r = i/K_AUG, c = i%K_AUG;
        g_kw0[i] = (c < 387) ? __float2half_rn(kw0[r*387 + c]) : __half(0.f); return; }
    i -= 512*K_AUG;
    if (i < 512*512) { g_kw1[i] = __float2half_rn(kw1[i]); return; }  i -= 512*512;
    if (i < 768*K_FIN) { int r = i/K_FIN, c = i%K_FIN;
        g_fw0[i] = (c < 515) ? __float2half_rn(fw0[r*515 + c]) : __half(0.f); return; }
    i -= 768*K_FIN;
    if (i < 1024*768) g_fw1[i] = __float2half_rn(fw1[i]);
}

// ---------------- step 1: per-point top-3 nearest SOM nodes + seg sums ----
__global__ void k_assign(const float* __restrict__ x, const float* __restrict__ node) {
    int b  = blockIdx.y;
    int n  = blockIdx.x*blockDim.x + threadIdx.x;
    int tid = threadIdx.x;
    __shared__ float snode[3][Mm];
    __shared__ float scnt[Mm];
    __shared__ float ssum[3][Mm];
    if (tid < 3*Mm) { int c = tid/Mm, m = tid%Mm; snode[c][m] = node[(b*3+c)*Mm+m]; }
    if (tid < Mm)   scnt[tid] = 0.f;
    if (tid < 3*Mm) ((float*)ssum)[tid] = 0.f;
    __syncthreads();

    float x0 = x[(b*3+0)*Nn+n], x1 = x[(b*3+1)*Nn+n], x2 = x[(b*3+2)*Nn+n];
    float d0 = 1e30f, d1 = 1e30f, d2 = 1e30f;
    int   i0 = 0, i1 = 0, i2 = 0;
    #pragma unroll 8
    for (int m = 0; m < Mm; m++) {
        float dx = x0 - snode[0][m], dy = x1 - snode[1][m], dz = x2 - snode[2][m];
        float d = dx*dx + dy*dy + dz*dz;
        if (d < d2) {
            if (d < d1) {
                if (d < d0) { d2=d1; i2=i1; d1=d0; i1=i0; d0=d; i0=m; }
                else        { d2=d1; i2=i1; d1=d;  i1=m; }
            } else          { d2=d;  i2=m; }
        }
    }
    g_seg[b*KN + 0*Nn + n] = b*Mm + i0;
    g_seg[b*KN + 1*Nn + n] = b*Mm + i1;
    g_seg[b*KN + 2*Nn + n] = b*Mm + i2;

    atomicAdd(&scnt[i0], 1.f); atomicAdd(&scnt[i1], 1.f); atomicAdd(&scnt[i2], 1.f);
    atomicAdd(&ssum[0][i0], x0); atomicAdd(&ssum[1][i0], x1); atomicAdd(&ssum[2][i0], x2);
    atomicAdd(&ssum[0][i1], x0); atomicAdd(&ssum[1][i1], x1); atomicAdd(&ssum[2][i1], x2);
    atomicAdd(&ssum[0][i2], x0); atomicAdd(&ssum[1][i2], x1); atomicAdd(&ssum[2][i2], x2);
    __syncthreads();
    if (tid < Mm)   atomicAdd(&g_cnt[b*Mm+tid], scnt[tid]);
    if (tid < 3*Mm) { int c = tid/Mm, m = tid%Mm; atomicAdd(&g_sum[(b*3+c)*Mm+m], ssum[c][m]); }
}

__global__ void k_mean() {
    int i = blockIdx.x*blockDim.x + threadIdx.x;
    if (i >= Bb*3*Mm) return;
    int m = i % Mm; int b = (i/Mm)/3;
    g_cmean[i] = g_sum[i] / (g_cnt[b*Mm+m] + EPSF);
}

// ---------------- fused layer-0: xaug + 64x6 conv + relu -> fp16 ----------
__global__ void k_l0(const float* __restrict__ x, const float* __restrict__ sn,
                     const float* __restrict__ w0, const float* __restrict__ b0) {
    __shared__ float sw[64*6];
    __shared__ float sb[64];
    int tid = threadIdx.x;
    for (int i = tid; i < 64*6; i += blockDim.x) sw[i] = w0[i];  // FIXED: full 384 loads
    if (tid < 64) sb[tid] = b0[tid];
    __syncthreads();
    int p = blockIdx.x*blockDim.x + tid;
    int n = p % Nn; int b = p / KN;
    int nm = g_seg[p] % Mm;
    float in[6];
    #pragma unroll
    for (int c = 0; c < 3; c++) {
        in[c]   = x[(b*3+c)*Nn+n] - g_cmean[(b*3+c)*Mm+nm];
        in[3+c] = sn[(b*3+c)*Nn+n];
    }
    #pragma unroll
    for (int o = 0; o < 64; o++) {
        float a = sb[o];
        #pragma unroll
        for (int c = 0; c < 6; c++) a += sw[o*6+c]*in[c];
        g_h02[(size_t)o*PTOT + p] = __float2half_rn(fmaxf(a, 0.f));
    }
}

// ---------------- fp16 HMMA GEMM -------------------------------------------
// C[Md x Nd] = relu(A[Md x Kd](fp16 row-major) * B[Kd x Nd](fp16 ch-major) + bias)
// OUT=0: fp16 C (channel-major, pitch Nd); OUT=1: fp32 C; OUT=2: segmax scatter.
#define APITCH 40   // halves per A smem row (80B; 16B-aligned, LDSM conflict-free)

template<int OUT>
__global__ __launch_bounds__(256, 2)
void k_hgemm(const __half* __restrict__ A, const __half* __restrict__ Bm,
             const float* __restrict__ bias, void* __restrict__ C,
             int Nd, int Kd) {
    __shared__ __align__(1024) __half As[2][128*APITCH];
    __shared__ __align__(1024) __half Bs[2][32*128];
    const int tid  = threadIdx.x;
    const int lane = tid & 31, warp = tid >> 5;
    const int wm = warp & 3, wn = warp >> 2;          // 4 (M) x 2 (N) warps
    const int rowBase = blockIdx.y * 128;
    const int colBase = blockIdx.x * 128;
    const uint32_t sA[2] = { smem_u32(As[0]), smem_u32(As[1]) };
    const uint32_t sB[2] = { smem_u32(Bs[0]), smem_u32(Bs[1]) };

    float acc[2][8][4];
    #pragma unroll
    for (int i = 0; i < 2; i++)
        #pragma unroll
        for (int j = 0; j < 8; j++)
            #pragma unroll
            for (int l = 0; l < 4; l++) acc[i][j][l] = 0.f;

    const int nT = Kd / 32;
    const __half* Arow = A + (size_t)rowBase*Kd;
    const __half* Brow = Bm + colBase;

    auto loadStage = [&](int t, int s) {
        // A: 128 rows x 32 halves (64B) -> 512 chunks of 16B
        #pragma unroll
        for (int i = 0; i < 2; i++) {
            int e = tid + i*256; int r = e >> 2, c = e & 3;
            CPA16(sA[s] + (uint32_t)(r*APITCH*2 + c*16),
                  (const char*)(Arow + (size_t)r*Kd + t*32 + c*8));
        }
        // B: 32 k-rows x 128 n (256B rows), XOR-swizzled chunk = c ^ (k&7)
        #pragma unroll
        for (int i = 0; i < 2; i++) {
            int e = tid + i*256; int k = e >> 4, c = e & 15;
            uint32_t off = (uint32_t)(k*256 + c*16);
            off ^= ((uint32_t)(k & 7)) << 4;
            CPA16(sB[s] + off, (const char*)(Brow + (size_t)(t*32 + k)*Nd + c*8));
        }
    };

    loadStage(0, 0); CPA_COMMIT();
    for (int t = 0; t < nT; t++) {
        if (t + 1 < nT) { loadStage(t + 1, (t + 1) & 1); CPA_COMMIT(); CPA_WAIT(1); }
        else            { CPA_WAIT(0); }
        __syncthreads();
        int buf = t & 1;
        #pragma unroll
        for (int ks = 0; ks < 2; ks++) {       // two k16 steps per k32 tile
            int kk = ks * 16;
            int mat = lane >> 3, r8 = lane & 7;
            // A fragments (no-trans): 2 m-tiles
            uint32_t aF[2][4];
            #pragma unroll
            for (int mt = 0; mt < 2; mt++) {
                int row = wm*32 + mt*16 + r8 + ((mat & 1) << 3);
                int kof = kk + ((mat >> 1) << 3);
                LDSM4(aF[mt][0], aF[mt][1], aF[mt][2], aF[mt][3],
                      sA[buf] + (uint32_t)(row*APITCH*2 + kof*2));
            }
            // B fragments (trans): 4 x4 loads cover 64 n cols
            uint32_t bF[4][4];
            #pragma unroll
            for (int q = 0; q < 4; q++) {
                int k = kk + r8 + ((mat & 1) << 3);
                int n = wn*64 + q*16 + ((mat >> 1) << 3);
                uint32_t off = (uint32_t)(k*256 + n*2);
                off ^= ((uint32_t)(k & 7)) << 4;
                LDSM4T(bF[q][0], bF[q][1], bF[q][2], bF[q][3], sB[buf] + off);
            }
            #pragma unroll
            for (int nt = 0; nt < 8; nt++) {
                uint32_t b0 = bF[nt >> 1][(nt & 1)*2];
                uint32_t b1 = bF[nt >> 1][(nt & 1)*2 + 1];
                #pragma unroll
                for (int mt = 0; mt < 2; mt++)
                    mma16816(acc[mt][nt], aF[mt][0], aF[mt][1], aF[mt][2], aF[mt][3], b0, b1);
            }
        }
        __syncthreads();
    }

    // epilogue
    #pragma unroll
    for (int mt = 0; mt < 2; mt++) {
        int r0 = rowBase + wm*32 + mt*16 + (lane >> 2);
        float bv0 = bias[r0], bv1 = bias[r0 + 8];
        #pragma unroll
        for (int nt = 0; nt < 8; nt++) {
            int n0 = colBase + wn*64 + nt*8 + 2*(lane & 3);
            float v00 = fmaxf(acc[mt][nt][0] + bv0, 0.f);
            float v01 = fmaxf(acc[mt][nt][1] + bv0, 0.f);
            float v10 = fmaxf(acc[mt][nt][2] + bv1, 0.f);
            float v11 = fmaxf(acc[mt][nt][3] + bv1, 0.f);
            if (OUT == 0) {
                __half* Ch = (__half*)C;
                *(__half2*)&Ch[(size_t)r0*Nd + n0]       = __floats2half2_rn(v00, v01);
                *(__half2*)&Ch[(size_t)(r0 + 8)*Nd + n0] = __floats2half2_rn(v10, v11);
            } else if (OUT == 1) {
                float* Cf = (float*)C;
                *(float2*)&Cf[(size_t)r0*Nd + n0]       = make_float2(v00, v01);
                *(float2*)&Cf[(size_t)(r0 + 8)*Nd + n0] = make_float2(v10, v11);
            } else {
                int s0 = g_seg[n0], s1 = g_seg[n0 + 1];
                atomicMax((int*)&g_nodeMax[(size_t)s0*384 + r0],     __float_as_int(v00));
                atomicMax((int*)&g_nodeMax[(size_t)s1*384 + r0],     __float_as_int(v01));
                atomicMax((int*)&g_nodeMax[(size_t)s0*384 + r0 + 8], __float_as_int(v10));
                atomicMax((int*)&g_nodeMax[(size_t)s1*384 + r0 + 8], __float_as_int(v11));
                if ((n0 % KN) == 0) {
                    g_first0[(n0/KN)*384 + r0]     = v00;
                    g_first0[(n0/KN)*384 + r0 + 8] = v10;
                }
            }
        }
    }
}

// ---------------- KNN module prep ------------------------------------------
__global__ void k_center(const int* __restrict__ I) {
    int i = blockIdx.x*blockDim.x + threadIdx.x;
    if (i >= Bb*3*Mm) return;
    int m = i % Mm; int bc = i / Mm; int b = bc/3; int c = bc%3;
    float s = 0.f;
    #pragma unroll
    for (int kk = 0; kk < SOMK; kk++) {
        int im = I[(b*Mm+m)*SOMK + kk];
        s += g_cmean[(b*3+c)*Mm + im];
    }
    g_center[i] = s * (1.0f/SOMK);
}

// channel-major fp16 aug [c][q], zero-padded rows 387..415
__global__ void k_aug(const int* __restrict__ I) {
    int t = blockIdx.x*blockDim.x + threadIdx.x;
    if (t >= K_AUG*QTOT) return;
    int q = t % QTOT, c = t / QTOT;
    float v = 0.f;
    if (c < 387) {
        int kk = q % SOMK; int bm = q / SOMK; int b = bm / Mm; int m = bm % Mm;
        int im = I[bm*SOMK + kk];
        if (c < 3)
            v = g_cmean[(b*3+c)*Mm + im] - g_center[(b*3+c)*Mm + m];
        else
            v = (g_cnt[b*Mm+im] > 0.f) ? g_nodeMax[(size_t)(b*Mm+im)*384 + (c-3)]
                                       : g_first0[b*384 + (c-3)];
    }
    g_aug[t] = __float2half_rn(v);
}

// max over som_k + final PointNet input [c][r], zero-padded rows 515..543
__global__ void k_finin() {
    int t = blockIdx.x*blockDim.x + threadIdx.x;
    if (t >= K_FIN*RTOT) return;
    int r = t % RTOT, c = t / RTOT;
    float v = 0.f;
    if (c < 3) {
        int b = r / Mm, m = r % Mm;
        v = g_center[(b*3+c)*Mm + m];
    } else if (c < 515) {
        float mx = -1e30f;
        size_t base = (size_t)(c-3)*QTOT + (size_t)r*SOMK;
        #pragma unroll
        for (int kk = 0; kk < SOMK; kk++) mx = fmaxf(mx, __half2float(g_g2[base+kk]));
        v = mx;
    }
    g_finin[t] = __float2half_rn(v);
}

// global max pool over M nodes -> output (B,1024)
__global__ void k_out(float* __restrict__ out) {
    int t = blockIdx.x*blockDim.x + threadIdx.x;
    if (t >= Bb*1024) return;
    int c = t % 1024, b = t / 1024;
    float mx = -1e30f;
    #pragma unroll 8
    for (int m = 0; m < Mm; m++) mx = fmaxf(mx, g_f2[(size_t)c*RTOT + b*Mm + m]);
    out[t] = mx;
}

// ---------------- launch ----------------------------------------------------
extern "C" void kernel_launch(void* const* d_in, const int* in_sizes, int n_in,
                              void* d_out, int out_size) {
    const float* x      = (const float*)d_in[0];
    const float* sn     = (const float*)d_in[1];
    const float* node   = (const float*)d_in[2];
    const int*   knnI   = (const int*)  d_in[3];
    const float* pr_w0  = (const float*)d_in[4];
    const float* pr_b0  = (const float*)d_in[5];
    const float* pr_w1  = (const float*)d_in[6];
    const float* pr_b1  = (const float*)d_in[7];
    const float* pr_w2  = (const float*)d_in[8];
    const float* pr_b2  = (const float*)d_in[9];
    const float* pr_w3  = (const float*)d_in[10];
    const float* pr_b3  = (const float*)d_in[11];
    const float* knn_w0 = (const float*)d_in[12];
    const float* knn_b0 = (const float*)d_in[13];
    const float* knn_w1 = (const float*)d_in[14];
    const float* knn_b1 = (const float*)d_in[15];
    const float* fin_w0 = (const float*)d_in[16];
    const float* fin_b0 = (const float*)d_in[17];
    const float* fin_w1 = (const float*)d_in[18];
    const float* fin_b1 = (const float*)d_in[19];
    float* out = (float*)d_out;

    __half *p_h02, *p_h1, *p_aug, *p_g1, *p_g2, *p_finin, *p_f1;
    __half *p_w1, *p_w2, *p_w3, *p_kw0, *p_kw1, *p_fw0, *p_fw1;
    float  *p_f2;
    cudaGetSymbolAddress((void**)&p_h02,   g_h02);
    cudaGetSymbolAddress((void**)&p_h1,    g_h1);
    cudaGetSymbolAddress((void**)&p_aug,   g_aug);
    cudaGetSymbolAddress((void**)&p_g1,    g_g1);
    cudaGetSymbolAddress((void**)&p_g2,    g_g2);
    cudaGetSymbolAddress((void**)&p_finin, g_finin);
    cudaGetSymbolAddress((void**)&p_f1,    g_f1);
    cudaGetSymbolAddress((void**)&p_f2,    g_f2);
    cudaGetSymbolAddress((void**)&p_w1,    g_w1);
    cudaGetSymbolAddress((void**)&p_w2,    g_w2);
    cudaGetSymbolAddress((void**)&p_w3,    g_w3);
    cudaGetSymbolAddress((void**)&p_kw0,   g_kw0);
    cudaGetSymbolAddress((void**)&p_kw1,   g_kw1);
    cudaGetSymbolAddress((void**)&p_fw0,   g_fw0);
    cudaGetSymbolAddress((void**)&p_fw1,   g_fw1);

    k_zero_stats  <<<(Bb*3*Mm + 255)/256, 256>>>();
    k_zero_nodemax<<<(RTOT*384 + 255)/256, 256>>>();
    {
        int wtot = 128*64 + 256*128 + 384*320 + 512*K_AUG + 512*512 + 768*K_FIN + 1024*768;
        k_wprep<<<(wtot + 255)/256, 256>>>(pr_w1, pr_w2, pr_w3, knn_w0, knn_w1, fin_w0, fin_w1);
    }

    k_assign<<<dim3(Nn/256, Bb), 256>>>(x, node);
    k_mean  <<<(Bb*3*Mm + 255)/256, 256>>>();
    k_l0    <<<PTOT/256, 256>>>(x, sn, pr_w0, pr_b0);

    // PointResNet (HMMA fp16)
    k_hgemm<0><<<dim3(PTOT/128, 1), 256>>>(p_w1, p_h02, pr_b1, p_h1, PTOT, 64);
    k_hgemm<0><<<dim3(PTOT/128, 2), 256>>>(p_w2, p_h1,  pr_b2, p_h02 + (size_t)64*PTOT, PTOT, 128);
    k_hgemm<2><<<dim3(PTOT/128, 3), 256>>>(p_w3, p_h02, pr_b3, nullptr, PTOT, 320);

    // KNN module over SOM nodes
    k_center<<<(Bb*3*Mm + 255)/256, 256>>>(knnI);
    k_aug   <<<(K_AUG*QTOT + 255)/256, 256>>>(knnI);
    k_hgemm<0><<<dim3(QTOT/128, 4), 256>>>(p_kw0, p_aug, knn_b0, p_g1, QTOT, K_AUG);
    k_hgemm<0><<<dim3(QTOT/128, 4), 256>>>(p_kw1, p_g1,  knn_b1, p_g2, QTOT, 512);

    // final PointNet + global max
    k_finin<<<(K_FIN*RTOT + 255)/256, 256>>>();
    k_hgemm<0><<<dim3(RTOT/128, 6), 256>>>(p_fw0, p_finin, fin_b0, p_f1, RTOT, K_FIN);
    k_hgemm<1><<<dim3(RTOT/128, 8), 256>>>(p_fw1, p_f1,    fin_b1, p_f2, RTOT, 768);
    k_out<<<(Bb*1024 + 255)/256, 256>>>(out);
}

// round 6
// speedup vs baseline: 9.6467x; 1.0807x over previous
#include <cuda_runtime.h>
#include <cuda_fp16.h>
#include <cstdint>

// ---------------- problem dims --------------------------------------------
#define Bb   8
#define Nn   8192
#define Mm   64
#define KQ   3
#define KN   (KQ*Nn)        // 24576
#define PTOT (Bb*KN)        // 196608
#define SOMK 9
#define QTOT (Bb*Mm*SOMK)   // 4608
#define RTOT (Bb*Mm)        // 512
#define EPSF 1e-5f
#define K_AUG 416
#define K_FIN 544

// ---------------- scratch (device globals; no allocation) -----------------
__device__ __half g_h02[(size_t)320*PTOT];
__device__ __half g_h1[(size_t)128*PTOT];
__device__ int    g_seg[PTOT];
__device__ float  g_cnt[Bb*Mm];
__device__ float  g_sum[Bb*3*Mm];
__device__ float  g_cmean[Bb*3*Mm];
__device__ float  g_center[Bb*3*Mm];
__device__ float  g_nodeMax[RTOT*384];
__device__ float  g_first0[Bb*384];
__device__ __half g_aug[(size_t)K_AUG*QTOT];
__device__ __half g_g1[(size_t)512*QTOT];
__device__ __half g_g2[(size_t)512*QTOT];
__device__ __half g_finin[(size_t)K_FIN*RTOT];
__device__ __half g_f1[(size_t)768*RTOT];
__device__ float  g_f2[(size_t)1024*RTOT];
__device__ __half g_w1[128*64];
__device__ __half g_w2[256*128];
__device__ __half g_w3[384*320];
__device__ __half g_kw0[512*K_AUG];
__device__ __half g_kw1[512*512];
__device__ __half g_fw0[768*K_FIN];
__device__ __half g_fw1[1024*768];

// ---------------- PTX helpers ---------------------------------------------
__device__ __forceinline__ uint32_t smem_u32(const void* p) {
    uint32_t a;
    asm("{ .reg .u64 t; cvta.to.shared.u64 t, %1; cvt.u32.u64 %0, t; }" : "=r"(a) : "l"(p));
    return a;
}
#define CPA16(dst, src) \
    asm volatile("cp.async.cg.shared.global [%0], [%1], 16;" :: "r"(dst), "l"(src))
#define CPA_COMMIT() asm volatile("cp.async.commit_group;" ::: "memory")
#define CPA_WAIT(n)  asm volatile("cp.async.wait_group %0;" :: "n"(n) : "memory")

#define LDSM4(r0,r1,r2,r3,addr) \
    asm volatile("ldmatrix.sync.aligned.m8n8.x4.shared.b16 {%0,%1,%2,%3}, [%4];" \
        : "=r"(r0), "=r"(r1), "=r"(r2), "=r"(r3) : "r"(addr))
#define LDSM4T(r0,r1,r2,r3,addr) \
    asm volatile("ldmatrix.sync.aligned.m8n8.x4.trans.shared.b16 {%0,%1,%2,%3}, [%4];" \
        : "=r"(r0), "=r"(r1), "=r"(r2), "=r"(r3) : "r"(addr))

__device__ __forceinline__ void mma16816(float c[4], uint32_t a0, uint32_t a1,
                                         uint32_t a2, uint32_t a3,
                                         uint32_t b0, uint32_t b1) {
    asm volatile(
        "mma.sync.aligned.m16n8k16.row.col.f32.f16.f16.f32 "
        "{%0,%1,%2,%3}, {%4,%5,%6,%7}, {%8,%9}, {%0,%1,%2,%3};"
        : "+f"(c[0]), "+f"(c[1]), "+f"(c[2]), "+f"(c[3])
        : "r"(a0), "r"(a1), "r"(a2), "r"(a3), "r"(b0), "r"(b1));
}

// ---------------- zero kernels --------------------------------------------
__global__ void k_zero_stats() {
    int i = blockIdx.x*blockDim.x + threadIdx.x;
    if (i < Bb*Mm)   g_cnt[i] = 0.f;
    if (i < Bb*3*Mm) g_sum[i] = 0.f;
}
__global__ void k_zero_nodemax() {
    int i = blockIdx.x*blockDim.x + threadIdx.x;
    if (i < RTOT*384) g_nodeMax[i] = 0.f;
}

// ---------------- weight prep ----------------------------------------------
__global__ void k_wprep(const float* __restrict__ w1, const float* __restrict__ w2,
                        const float* __restrict__ w3, const float* __restrict__ kw0,
                        const float* __restrict__ kw1, const float* __restrict__ fw0,
                        const float* __restrict__ fw1) {
    int i = blockIdx.x*blockDim.x + threadIdx.x;
    if (i < 128*64)  { g_w1[i] = __float2half_rn(w1[i]); return; }  i -= 128*64;
    if (i < 256*128) { g_w2[i] = __float2half_rn(w2[i]); return; }  i -= 256*128;
    if (i < 384*320) { g_w3[i] = __float2half_rn(w3[i]); return; }  i -= 384*320;
    if (i < 512*K_AUG) { int r = i/K_AUG, c = i%K_AUG;
        g_kw0[i] = (c < 387) ? __float2half_rn(kw0[r*387 + c]) : __half(0.f); return; }
    i -= 512*K_AUG;
    if (i < 512*512) { g_kw1[i] = __float2half_rn(kw1[i]); return; }  i -= 512*512;
    if (i < 768*K_FIN) { int r = i/K_FIN, c = i%K_FIN;
        g_fw0[i] = (c < 515) ? __float2half_rn(fw0[r*515 + c]) : __half(0.f); return; }
    i -= 768*K_FIN;
    if (i < 1024*768) g_fw1[i] = __float2half_rn(fw1[i]);
}

// ---------------- step 1: top-3 assignment + seg sums ----------------------
__global__ void k_assign(const float* __restrict__ x, const float* __restrict__ node) {
    int b  = blockIdx.y;
    int n  = blockIdx.x*blockDim.x + threadIdx.x;
    int tid = threadIdx.x;
    __shared__ float snode[3][Mm];
    __shared__ float scnt[Mm];
    __shared__ float ssum[3][Mm];
    if (tid < 3*Mm) { int c = tid/Mm, m = tid%Mm; snode[c][m] = node[(b*3+c)*Mm+m]; }
    if (tid < Mm)   scnt[tid] = 0.f;
    if (tid < 3*Mm) ((float*)ssum)[tid] = 0.f;
    __syncthreads();

    float x0 = x[(b*3+0)*Nn+n], x1 = x[(b*3+1)*Nn+n], x2 = x[(b*3+2)*Nn+n];
    float d0 = 1e30f, d1 = 1e30f, d2 = 1e30f;
    int   i0 = 0, i1 = 0, i2 = 0;
    #pragma unroll 8
    for (int m = 0; m < Mm; m++) {
        float dx = x0 - snode[0][m], dy = x1 - snode[1][m], dz = x2 - snode[2][m];
        float d = dx*dx + dy*dy + dz*dz;
        if (d < d2) {
            if (d < d1) {
                if (d < d0) { d2=d1; i2=i1; d1=d0; i1=i0; d0=d; i0=m; }
                else        { d2=d1; i2=i1; d1=d;  i1=m; }
            } else          { d2=d;  i2=m; }
        }
    }
    g_seg[b*KN + 0*Nn + n] = b*Mm + i0;
    g_seg[b*KN + 1*Nn + n] = b*Mm + i1;
    g_seg[b*KN + 2*Nn + n] = b*Mm + i2;

    atomicAdd(&scnt[i0], 1.f); atomicAdd(&scnt[i1], 1.f); atomicAdd(&scnt[i2], 1.f);
    atomicAdd(&ssum[0][i0], x0); atomicAdd(&ssum[1][i0], x1); atomicAdd(&ssum[2][i0], x2);
    atomicAdd(&ssum[0][i1], x0); atomicAdd(&ssum[1][i1], x1); atomicAdd(&ssum[2][i1], x2);
    atomicAdd(&ssum[0][i2], x0); atomicAdd(&ssum[1][i2], x1); atomicAdd(&ssum[2][i2], x2);
    __syncthreads();
    if (tid < Mm)   atomicAdd(&g_cnt[b*Mm+tid], scnt[tid]);
    if (tid < 3*Mm) { int c = tid/Mm, m = tid%Mm; atomicAdd(&g_sum[(b*3+c)*Mm+m], ssum[c][m]); }
}

__global__ void k_mean() {
    int i = blockIdx.x*blockDim.x + threadIdx.x;
    if (i >= Bb*3*Mm) return;
    int m = i % Mm; int b = (i/Mm)/3;
    g_cmean[i] = g_sum[i] / (g_cnt[b*Mm+m] + EPSF);
}

// ---------------- fused layer-0 --------------------------------------------
__global__ void k_l0(const float* __restrict__ x, const float* __restrict__ sn,
                     const float* __restrict__ w0, const float* __restrict__ b0) {
    __shared__ float sw[64*6];
    __shared__ float sb[64];
    int tid = threadIdx.x;
    for (int i = tid; i < 64*6; i += blockDim.x) sw[i] = w0[i];
    if (tid < 64) sb[tid] = b0[tid];
    __syncthreads();
    int p = blockIdx.x*blockDim.x + tid;
    int n = p % Nn; int b = p / KN;
    int nm = g_seg[p] % Mm;
    float in[6];
    #pragma unroll
    for (int c = 0; c < 3; c++) {
        in[c]   = x[(b*3+c)*Nn+n] - g_cmean[(b*3+c)*Mm+nm];
        in[3+c] = sn[(b*3+c)*Nn+n];
    }
    #pragma unroll
    for (int o = 0; o < 64; o++) {
        float a = sb[o];
        #pragma unroll
        for (int c = 0; c < 6; c++) a += sw[o*6+c]*in[c];
        g_h02[(size_t)o*PTOT + p] = __float2half_rn(fmaxf(a, 0.f));
    }
}

// ---------------- fp16 HMMA GEMM -------------------------------------------
// OUT=0: fp16 C; OUT=1: fp32 C; OUT=2: smem segment-max + single flush.
// NX: number of 128-col tiles per CTA (OUT==2 uses 8 -> 1024-col window).
#define APITCH 40
#define A_STG (128*APITCH*2)     // 10240 B
#define B_STG (32*128*2)         // 8192 B
#define SMEM_BASE (2*A_STG + 2*B_STG)          // 36864
#define SMEM_SEG  (SMEM_BASE + 64*128*4)       // + 32768 = 69632

template<int OUT, int NX>
__global__ __launch_bounds__(256, 2)
void k_hgemm(const __half* __restrict__ A, const __half* __restrict__ Bm,
             const float* __restrict__ bias, void* __restrict__ C,
             int Nd, int Kd) {
    extern __shared__ __align__(1024) char dsm[];
    const uint32_t base = smem_u32(dsm);
    const uint32_t sA[2] = { base,            base + A_STG };
    const uint32_t sB[2] = { base + 2*A_STG,  base + 2*A_STG + B_STG };
    float* smax = (float*)(dsm + SMEM_BASE);   // [64 nodes][128 rows], OUT==2 only

    const int tid  = threadIdx.x;
    const int lane = tid & 31, warp = tid >> 5;
    const int wm = warp & 3, wn = warp >> 2;
    const int rowBase = blockIdx.y * 128;
    const int colBase = blockIdx.x * (128*NX);
    const int nT = Kd / 32;
    const __half* Arow = A + (size_t)rowBase*Kd;

    if (OUT == 2) {
        for (int i = tid; i < 64*128; i += 256) smax[i] = 0.f;
        // no extra sync needed: first epilogue is far behind many __syncthreads
        __syncthreads();
    }

    for (int nx = 0; nx < NX; nx++) {
        const int cb = colBase + nx*128;
        const __half* Brow = Bm + cb;

        float acc[2][8][4];
        #pragma unroll
        for (int i = 0; i < 2; i++)
            #pragma unroll
            for (int j = 0; j < 8; j++)
                #pragma unroll
                for (int l = 0; l < 4; l++) acc[i][j][l] = 0.f;

        auto loadStage = [&](int t, int s) {
            #pragma unroll
            for (int i = 0; i < 2; i++) {
                int e = tid + i*256; int r = e >> 2, c = e & 3;
                CPA16(sA[s] + (uint32_t)(r*APITCH*2 + c*16),
                      (const char*)(Arow + (size_t)r*Kd + t*32 + c*8));
            }
            #pragma unroll
            for (int i = 0; i < 2; i++) {
                int e = tid + i*256; int k = e >> 4, c = e & 15;
                uint32_t off = (uint32_t)(k*256 + c*16);
                off ^= ((uint32_t)(k & 7)) << 4;
                CPA16(sB[s] + off, (const char*)(Brow + (size_t)(t*32 + k)*Nd + c*8));
            }
        };

        loadStage(0, 0); CPA_COMMIT();
        for (int t = 0; t < nT; t++) {
            if (t + 1 < nT) { loadStage(t + 1, (t + 1) & 1); CPA_COMMIT(); CPA_WAIT(1); }
            else            { CPA_WAIT(0); }
            __syncthreads();
            int buf = t & 1;
            #pragma unroll
            for (int ks = 0; ks < 2; ks++) {
                int kk = ks * 16;
                int mat = lane >> 3, r8 = lane & 7;
                uint32_t aF[2][4];
                #pragma unroll
                for (int mt = 0; mt < 2; mt++) {
                    int row = wm*32 + mt*16 + r8 + ((mat & 1) << 3);
                    int kof = kk + ((mat >> 1) << 3);
                    LDSM4(aF[mt][0], aF[mt][1], aF[mt][2], aF[mt][3],
                          sA[buf] + (uint32_t)(row*APITCH*2 + kof*2));
                }
                uint32_t bF[4][4];
                #pragma unroll
                for (int q = 0; q < 4; q++) {
                    int k = kk + r8 + ((mat & 1) << 3);
                    int n = wn*64 + q*16 + ((mat >> 1) << 3);
                    uint32_t off = (uint32_t)(k*256 + n*2);
                    off ^= ((uint32_t)(k & 7)) << 4;
                    LDSM4T(bF[q][0], bF[q][1], bF[q][2], bF[q][3], sB[buf] + off);
                }
                #pragma unroll
                for (int nt = 0; nt < 8; nt++) {
                    uint32_t b0 = bF[nt >> 1][(nt & 1)*2];
                    uint32_t b1 = bF[nt >> 1][(nt & 1)*2 + 1];
                    #pragma unroll
                    for (int mt = 0; mt < 2; mt++)
                        mma16816(acc[mt][nt], aF[mt][0], aF[mt][1], aF[mt][2], aF[mt][3], b0, b1);
                }
            }
            __syncthreads();
        }

        // epilogue for this 128-col tile
        #pragma unroll
        for (int mt = 0; mt < 2; mt++) {
            int lr0 = wm*32 + mt*16 + (lane >> 2);     // local row 0..127
            int r0 = rowBase + lr0;
            float bv0 = bias[r0], bv1 = bias[r0 + 8];
            #pragma unroll
            for (int nt = 0; nt < 8; nt++) {
                int n0 = cb + wn*64 + nt*8 + 2*(lane & 3);
                float v00 = fmaxf(acc[mt][nt][0] + bv0, 0.f);
                float v01 = fmaxf(acc[mt][nt][1] + bv0, 0.f);
                float v10 = fmaxf(acc[mt][nt][2] + bv1, 0.f);
                float v11 = fmaxf(acc[mt][nt][3] + bv1, 0.f);
                if (OUT == 0) {
                    __half* Ch = (__half*)C;
                    *(__half2*)&Ch[(size_t)r0*Nd + n0]       = __floats2half2_rn(v00, v01);
                    *(__half2*)&Ch[(size_t)(r0 + 8)*Nd + n0] = __floats2half2_rn(v10, v11);
                } else if (OUT == 1) {
                    float* Cf = (float*)C;
                    *(float2*)&Cf[(size_t)r0*Nd + n0]       = make_float2(v00, v01);
                    *(float2*)&Cf[(size_t)(r0 + 8)*Nd + n0] = make_float2(v10, v11);
                } else {
                    int s0 = g_seg[n0] & 63, s1 = g_seg[n0 + 1] & 63;
                    atomicMax((int*)&smax[s0*128 + lr0],     __float_as_int(v00));
                    atomicMax((int*)&smax[s1*128 + lr0],     __float_as_int(v01));
                    atomicMax((int*)&smax[s0*128 + lr0 + 8], __float_as_int(v10));
                    atomicMax((int*)&smax[s1*128 + lr0 + 8], __float_as_int(v11));
                    if ((n0 % KN) == 0) {
                        g_first0[(n0/KN)*384 + r0]     = v00;
                        g_first0[(n0/KN)*384 + r0 + 8] = v10;
                    }
                }
            }
        }
        if (OUT == 2) __syncthreads();   // table updates done before next tile reuse
    }

    if (OUT == 2) {
        // flush per-window table to global (skip zeros: g_nodeMax zero-initialized)
        int bIdx = colBase / KN;
        for (int i = tid; i < 64*128; i += 256) {
            float v = smax[i];
            if (v > 0.f) {
                int node = i >> 7, lr = i & 127;
                atomicMax((int*)&g_nodeMax[(size_t)(bIdx*Mm + node)*384 + rowBase + lr],
                          __float_as_int(v));
            }
        }
    }
}

// ---------------- KNN module prep ------------------------------------------
__global__ void k_center(const int* __restrict__ I) {
    int i = blockIdx.x*blockDim.x + threadIdx.x;
    if (i >= Bb*3*Mm) return;
    int m = i % Mm; int bc = i / Mm; int b = bc/3; int c = bc%3;
    float s = 0.f;
    #pragma unroll
    for (int kk = 0; kk < SOMK; kk++) {
        int im = I[(b*Mm+m)*SOMK + kk];
        s += g_cmean[(b*3+c)*Mm + im];
    }
    g_center[i] = s * (1.0f/SOMK);
}

__global__ void k_aug(const int* __restrict__ I) {
    int t = blockIdx.x*blockDim.x + threadIdx.x;
    if (t >= K_AUG*QTOT) return;
    int q = t % QTOT, c = t / QTOT;
    float v = 0.f;
    if (c < 387) {
        int kk = q % SOMK; int bm = q / SOMK; int b = bm / Mm; int m = bm % Mm;
        int im = I[bm*SOMK + kk];
        if (c < 3)
            v = g_cmean[(b*3+c)*Mm + im] - g_center[(b*3+c)*Mm + m];
        else
            v = (g_cnt[b*Mm+im] > 0.f) ? g_nodeMax[(size_t)(b*Mm+im)*384 + (c-3)]
                                       : g_first0[b*384 + (c-3)];
    }
    g_aug[t] = __float2half_rn(v);
}

__global__ void k_finin() {
    int t = blockIdx.x*blockDim.x + threadIdx.x;
    if (t >= K_FIN*RTOT) return;
    int r = t % RTOT, c = t / RTOT;
    float v = 0.f;
    if (c < 3) {
        int b = r / Mm, m = r % Mm;
        v = g_center[(b*3+c)*Mm + m];
    } else if (c < 515) {
        float mx = -1e30f;
        size_t base = (size_t)(c-3)*QTOT + (size_t)r*SOMK;
        #pragma unroll
        for (int kk = 0; kk < SOMK; kk++) mx = fmaxf(mx, __half2float(g_g2[base+kk]));
        v = mx;
    }
    g_finin[t] = __float2half_rn(v);
}

__global__ void k_out(float* __restrict__ out) {
    int t = blockIdx.x*blockDim.x + threadIdx.x;
    if (t >= Bb*1024) return;
    int c = t % 1024, b = t / 1024;
    float mx = -1e30f;
    #pragma unroll 8
    for (int m = 0; m < Mm; m++) mx = fmaxf(mx, g_f2[(size_t)c*RTOT + b*Mm + m]);
    out[t] = mx;
}

// ---------------- launch ----------------------------------------------------
extern "C" void kernel_launch(void* const* d_in, const int* in_sizes, int n_in,
                              void* d_out, int out_size) {
    const float* x      = (const float*)d_in[0];
    const float* sn     = (const float*)d_in[1];
    const float* node   = (const float*)d_in[2];
    const int*   knnI   = (const int*)  d_in[3];
    const float* pr_w0  = (const float*)d_in[4];
    const float* pr_b0  = (const float*)d_in[5];
    const float* pr_w1  = (const float*)d_in[6];
    const float* pr_b1  = (const float*)d_in[7];
    const float* pr_w2  = (const float*)d_in[8];
    const float* pr_b2  = (const float*)d_in[9];
    const float* pr_w3  = (const float*)d_in[10];
    const float* pr_b3  = (const float*)d_in[11];
    const float* knn_w0 = (const float*)d_in[12];
    const float* knn_b0 = (const float*)d_in[13];
    const float* knn_w1 = (const float*)d_in[14];
    const float* knn_b1 = (const float*)d_in[15];
    const float* fin_w0 = (const float*)d_in[16];
    const float* fin_b0 = (const float*)d_in[17];
    const float* fin_w1 = (const float*)d_in[18];
    const float* fin_b1 = (const float*)d_in[19];
    float* out = (float*)d_out;

    __half *p_h02, *p_h1, *p_aug, *p_g1, *p_g2, *p_finin, *p_f1;
    __half *p_w1, *p_w2, *p_w3, *p_kw0, *p_kw1, *p_fw0, *p_fw1;
    float  *p_f2;
    cudaGetSymbolAddress((void**)&p_h02,   g_h02);
    cudaGetSymbolAddress((void**)&p_h1,    g_h1);
    cudaGetSymbolAddress((void**)&p_aug,   g_aug);
    cudaGetSymbolAddress((void**)&p_g1,    g_g1);
    cudaGetSymbolAddress((void**)&p_g2,    g_g2);
    cudaGetSymbolAddress((void**)&p_finin, g_finin);
    cudaGetSymbolAddress((void**)&p_f1,    g_f1);
    cudaGetSymbolAddress((void**)&p_f2,    g_f2);
    cudaGetSymbolAddress((void**)&p_w1,    g_w1);
    cudaGetSymbolAddress((void**)&p_w2,    g_w2);
    cudaGetSymbolAddress((void**)&p_w3,    g_w3);
    cudaGetSymbolAddress((void**)&p_kw0,   g_kw0);
    cudaGetSymbolAddress((void**)&p_kw1,   g_kw1);
    cudaGetSymbolAddress((void**)&p_fw0,   g_fw0);
    cudaGetSymbolAddress((void**)&p_fw1,   g_fw1);

    cudaFuncSetAttribute(k_hgemm<0,1>, cudaFuncAttributeMaxDynamicSharedMemorySize, SMEM_BASE);
    cudaFuncSetAttribute(k_hgemm<1,1>, cudaFuncAttributeMaxDynamicSharedMemorySize, SMEM_BASE);
    cudaFuncSetAttribute(k_hgemm<2,8>, cudaFuncAttributeMaxDynamicSharedMemorySize, SMEM_SEG);

    k_zero_stats  <<<(Bb*3*Mm + 255)/256, 256>>>();
    k_zero_nodemax<<<(RTOT*384 + 255)/256, 256>>>();
    {
        int wtot = 128*64 + 256*128 + 384*320 + 512*K_AUG + 512*512 + 768*K_FIN + 1024*768;
        k_wprep<<<(wtot + 255)/256, 256>>>(pr_w1, pr_w2, pr_w3, knn_w0, knn_w1, fin_w0, fin_w1);
    }

    k_assign<<<dim3(Nn/256, Bb), 256>>>(x, node);
    k_mean  <<<(Bb*3*Mm + 255)/256, 256>>>();
    k_l0    <<<PTOT/256, 256>>>(x, sn, pr_w0, pr_b0);

    // PointResNet (HMMA fp16)
    k_hgemm<0,1><<<dim3(PTOT/128, 1), 256, SMEM_BASE>>>(p_w1, p_h02, pr_b1, p_h1, PTOT, 64);
    k_hgemm<0,1><<<dim3(PTOT/128, 2), 256, SMEM_BASE>>>(p_w2, p_h1,  pr_b2, p_h02 + (size_t)64*PTOT, PTOT, 128);
    k_hgemm<2,8><<<dim3(PTOT/1024, 3), 256, SMEM_SEG>>>(p_w3, p_h02, pr_b3, nullptr, PTOT, 320);

    // KNN module over SOM nodes
    k_center<<<(Bb*3*Mm + 255)/256, 256>>>(knnI);
    k_aug   <<<(K_AUG*QTOT + 255)/256, 256>>>(knnI);
    k_hgemm<0,1><<<dim3(QTOT/128, 4), 256, SMEM_BASE>>>(p_kw0, p_aug, knn_b0, p_g1, QTOT, K_AUG);
    k_hgemm<0,1><<<dim3(QTOT/128, 4), 256, SMEM_BASE>>>(p_kw1, p_g1,  knn_b1, p_g2, QTOT, 512);

    // final PointNet + global max
    k_finin<<<(K_FIN*RTOT + 255)/256, 256>>>();
    k_hgemm<0,1><<<dim3(RTOT/128, 6), 256, SMEM_BASE>>>(p_fw0, p_finin, fin_b0, p_f1, RTOT, K_FIN);
    k_hgemm<1,1><<<dim3(RTOT/128, 8), 256, SMEM_BASE>>>(p_fw1, p_f1,    fin_b1, p_f2, RTOT, 768);
    k_out<<<(Bb*1024 + 255)/256, 256>>>(out);
}